// round 1
// baseline (speedup 1.0000x reference)
#include <cuda_runtime.h>

#define NB   8
#define TGT  256
#define SRC  512
#define DIM  1024
#define NH   16
#define DH   64

// scratch for projected q/k (no cudaMalloc allowed)
__device__ float g_q[(size_t)NB * TGT * DIM];   // 8 MB
__device__ float g_k[(size_t)NB * SRC * DIM];   // 16 MB

// ---------------------------------------------------------------------------
// C[m,n] = relu( sum_k A[m,k]*W[n,k] + bias[n] ),  K = N = 1024
// 64x64 block tile, BK=16, 256 threads, 4x4 per thread.
// ---------------------------------------------------------------------------
__global__ __launch_bounds__(256) void gemm_relu_kernel(
    const float* __restrict__ A, const float* __restrict__ W,
    const float* __restrict__ bias, float* __restrict__ C) {
    __shared__ float As[16][64];
    __shared__ float Ws[16][64];
    const int tid = threadIdx.x;
    const int m0 = blockIdx.x * 64, n0 = blockIdx.y * 64;
    const int lr = tid >> 2;          // 0..63 row in tile
    const int lk = (tid & 3) << 2;    // 0,4,8,12
    const int tm = (tid & 15) << 2;   // m offset for compute
    const int tn = (tid >> 4) << 2;   // n offset for compute

    float acc[4][4] = {};
    const float* Ap = A + (size_t)(m0 + lr) * DIM + lk;
    const float* Wp = W + (size_t)(n0 + lr) * DIM + lk;

    for (int k0 = 0; k0 < DIM; k0 += 16) {
        float4 av = *(const float4*)(Ap + k0);
        float4 wv = *(const float4*)(Wp + k0);
        As[lk + 0][lr] = av.x; As[lk + 1][lr] = av.y;
        As[lk + 2][lr] = av.z; As[lk + 3][lr] = av.w;
        Ws[lk + 0][lr] = wv.x; Ws[lk + 1][lr] = wv.y;
        Ws[lk + 2][lr] = wv.z; Ws[lk + 3][lr] = wv.w;
        __syncthreads();
#pragma unroll
        for (int kk = 0; kk < 16; kk++) {
            float4 a = *(const float4*)&As[kk][tm];
            float4 w = *(const float4*)&Ws[kk][tn];
            acc[0][0] += a.x * w.x; acc[0][1] += a.x * w.y;
            acc[0][2] += a.x * w.z; acc[0][3] += a.x * w.w;
            acc[1][0] += a.y * w.x; acc[1][1] += a.y * w.y;
            acc[1][2] += a.y * w.z; acc[1][3] += a.y * w.w;
            acc[2][0] += a.z * w.x; acc[2][1] += a.z * w.y;
            acc[2][2] += a.z * w.z; acc[2][3] += a.z * w.w;
            acc[3][0] += a.w * w.x; acc[3][1] += a.w * w.y;
            acc[3][2] += a.w * w.z; acc[3][3] += a.w * w.w;
        }
        __syncthreads();
    }
    float4 bv = *(const float4*)(bias + n0 + tn);
#pragma unroll
    for (int i = 0; i < 4; i++) {
        float4 o;
        o.x = fmaxf(acc[i][0] + bv.x, 0.f);
        o.y = fmaxf(acc[i][1] + bv.y, 0.f);
        o.z = fmaxf(acc[i][2] + bv.z, 0.f);
        o.w = fmaxf(acc[i][3] + bv.w, 0.f);
        *(float4*)(C + (size_t)(m0 + tm + i) * DIM + n0 + tn) = o;
    }
}

// ---------------------------------------------------------------------------
// energy[bh, t, s] = (q[b,t,h,:] . k[b,s,h,:]) * 0.125 + eb
// p = sigmoid(energy * 5)
// One block per (s-tile=64, t-tile=64, bh). K = DH = 64 single pass.
// ---------------------------------------------------------------------------
__device__ __forceinline__ float sigmoid5(float e) {
    return 1.f / (1.f + __expf(-5.f * e));
}

__global__ __launch_bounds__(256) void energy_kernel(
    const float* __restrict__ ebias, float* __restrict__ p) {
    __shared__ float Qs[64][64];
    __shared__ float Ks[64][64];
    const int tid = threadIdx.x;
    const int s0 = blockIdx.x * 64;
    const int t0 = blockIdx.y * 64;
    const int bh = blockIdx.z;
    const int b = bh >> 4, h = bh & 15;

#pragma unroll
    for (int it = 0; it < 4; it++) {
        int idx = tid + it * 256;
        int row = idx >> 4;
        int c4  = (idx & 15) << 2;
        float4 qv = *(const float4*)(g_q + (size_t)(b * TGT + t0 + row) * DIM + h * DH + c4);
        Qs[c4 + 0][row] = qv.x; Qs[c4 + 1][row] = qv.y;
        Qs[c4 + 2][row] = qv.z; Qs[c4 + 3][row] = qv.w;
        float4 kv = *(const float4*)(g_k + (size_t)(b * SRC + s0 + row) * DIM + h * DH + c4);
        Ks[c4 + 0][row] = kv.x; Ks[c4 + 1][row] = kv.y;
        Ks[c4 + 2][row] = kv.z; Ks[c4 + 3][row] = kv.w;
    }
    __syncthreads();

    const int tm = (tid & 15) << 2;   // t offset
    const int tn = (tid >> 4) << 2;   // s offset
    float acc[4][4] = {};
#pragma unroll
    for (int kk = 0; kk < 64; kk++) {
        float4 a = *(const float4*)&Qs[kk][tm];
        float4 w = *(const float4*)&Ks[kk][tn];
        acc[0][0] += a.x * w.x; acc[0][1] += a.x * w.y;
        acc[0][2] += a.x * w.z; acc[0][3] += a.x * w.w;
        acc[1][0] += a.y * w.x; acc[1][1] += a.y * w.y;
        acc[1][2] += a.y * w.z; acc[1][3] += a.y * w.w;
        acc[2][0] += a.z * w.x; acc[2][1] += a.z * w.y;
        acc[2][2] += a.z * w.z; acc[2][3] += a.z * w.w;
        acc[3][0] += a.w * w.x; acc[3][1] += a.w * w.y;
        acc[3][2] += a.w * w.z; acc[3][3] += a.w * w.w;
    }
    const float eb = ebias[0];
#pragma unroll
    for (int i = 0; i < 4; i++) {
        float4 o;
        o.x = sigmoid5(acc[i][0] * 0.125f + eb);
        o.y = sigmoid5(acc[i][1] * 0.125f + eb);
        o.z = sigmoid5(acc[i][2] * 0.125f + eb);
        o.w = sigmoid5(acc[i][3] * 0.125f + eb);
        *(float4*)(p + ((size_t)bh * TGT + t0 + tm + i) * SRC + s0 + tn) = o;
    }
}

// ---------------------------------------------------------------------------
// Monotonic alignment. Per (bh): sequential over t, parallel affine scan
// over s:  c[n] = a[n]*c[n-1] + b[n],  a[n] = 1-p_t[n-1],  b[n] = alpha_{t-1}[n]
// alpha_t[n] = p_t[n]*c[n].  t=0 uses b[n] = (n==0).
// 256 threads, 2 src elements per thread (S=512). One block per bh.
// ---------------------------------------------------------------------------
__global__ __launch_bounds__(256) void align_kernel(
    const float* __restrict__ p, float* __restrict__ alpha) {
    const int bh = blockIdx.x;
    const int tid = threadIdx.x;
    const int lane = tid & 31, wid = tid >> 5;
    __shared__ float ps[SRC];
    __shared__ float wA[8], wB[8];

    const float* prow = p + (size_t)bh * TGT * SRC;
    float* arow = alpha + (size_t)bh * TGT * SRC;
    const int n0 = tid * 2;

    float b0 = (tid == 0) ? 1.f : 0.f;   // alpha_{-1}[n] = delta(n,0)
    float b1 = 0.f;

    for (int t = 0; t < TGT; t++) {
        float2 pv = *(const float2*)(prow + (size_t)t * SRC + n0);
        *(float2*)(ps + n0) = pv;
        __syncthreads();

        float a0 = (n0 == 0) ? 0.f : (1.f - ps[n0 - 1]);
        float a1 = 1.f - pv.x;

        // local composition over this thread's 2 elements
        float A  = a0 * a1;
        float Bv = b0 * a1 + b1;

        // warp inclusive scan of affine pairs
#pragma unroll
        for (int d = 1; d < 32; d <<= 1) {
            float Ap = __shfl_up_sync(0xffffffffu, A, d);
            float Bp = __shfl_up_sync(0xffffffffu, Bv, d);
            if (lane >= d) { Bv = Bp * A + Bv; A = Ap * A; }
        }
        if (lane == 31) { wA[wid] = A; wB[wid] = Bv; }
        __syncthreads();

        // exclusive cross-warp prefix (initial c = 0, so only B matters)
        float WB = 0.f;
        for (int w = 0; w < wid; w++) WB = WB * wA[w] + wB[w];

        // lane-exclusive pair within warp
        float EA = __shfl_up_sync(0xffffffffu, A, 1);
        float EB = __shfl_up_sync(0xffffffffu, Bv, 1);
        if (lane == 0) { EA = 1.f; EB = 0.f; }

        float cin = WB * EA + EB;        // c[n0-1]
        float c0 = a0 * cin + b0;
        float c1 = a1 * c0 + b1;
        float al0 = pv.x * c0;
        float al1 = pv.y * c1;
        *(float2*)(arow + (size_t)t * SRC + n0) = make_float2(al0, al1);
        b0 = al0; b1 = al1;
        __syncthreads();
    }
}

// ---------------------------------------------------------------------------
extern "C" void kernel_launch(void* const* d_in, const int* in_sizes, int n_in,
                              void* d_out, int out_size) {
    const float* seqs = (const float*)d_in[0];
    const float* keys = (const float*)d_in[1];
    const float* q_w  = (const float*)d_in[2];
    const float* q_b  = (const float*)d_in[3];
    const float* k_w  = (const float*)d_in[4];
    const float* k_b  = (const float*)d_in[5];
    const float* eb   = (const float*)d_in[6];

    float* out   = (float*)d_out;
    float* p     = out;                                   // (B,H,TGT,SRC)
    float* alpha = out + (size_t)NB * NH * TGT * SRC;     // (B,H,TGT,SRC)

    float *qp = nullptr, *kp = nullptr;
    cudaGetSymbolAddress((void**)&qp, g_q);
    cudaGetSymbolAddress((void**)&kp, g_k);

    // q = relu(seqs @ q_w^T + q_b): M = 8*256 = 2048
    gemm_relu_kernel<<<dim3(2048 / 64, DIM / 64), 256>>>(seqs, q_w, q_b, qp);
    // k = relu(keys @ k_w^T + k_b): M = 8*512 = 4096
    gemm_relu_kernel<<<dim3(4096 / 64, DIM / 64), 256>>>(keys, k_w, k_b, kp);
    // p_choose
    energy_kernel<<<dim3(SRC / 64, TGT / 64, NB * NH), 256>>>(eb, p);
    // alpha
    align_kernel<<<NB * NH, 256>>>(p, alpha);
}

// round 2
// speedup vs baseline: 1.1554x; 1.1554x over previous
#include <cuda_runtime.h>

#define NB   8
#define TGT  256
#define SRC  512
#define DIM  1024
#define NH   16
#define DH   64

typedef unsigned long long ull;

// scratch for projected q/k (no cudaMalloc allowed)
__device__ float g_q[(size_t)NB * TGT * DIM];   // 8 MB
__device__ float g_k[(size_t)NB * SRC * DIM];   // 16 MB

__device__ __forceinline__ ull ffma2(ull a, ull b, ull c) {
    ull d;
    asm("fma.rn.f32x2 %0, %1, %2, %3;" : "=l"(d) : "l"(a), "l"(b), "l"(c));
    return d;
}
__device__ __forceinline__ ull pack2(float x, float y) {
    ull d; asm("mov.b64 %0, {%1, %2};" : "=l"(d) : "f"(x), "f"(y)); return d;
}
__device__ __forceinline__ void unpack2(ull v, float& lo, float& hi) {
    asm("mov.b64 {%0, %1}, %2;" : "=f"(lo), "=f"(hi) : "l"(v));
}

// ---------------------------------------------------------------------------
// C[m,n] = relu( sum_k A[m,k]*W[n,k] + bias[n] ),  K = N = 1024
// 64x64 block tile, BK=16, 256 threads, 4x4 per thread, packed f32x2 FMA.
// M-pairs in the packed lanes, N duplicated.
// ---------------------------------------------------------------------------
__global__ __launch_bounds__(256) void gemm_relu_kernel(
    const float* __restrict__ A, const float* __restrict__ W,
    const float* __restrict__ bias, float* __restrict__ C) {
    __shared__ float As[16][64];
    __shared__ float Ws[16][64];
    const int tid = threadIdx.x;
    const int m0 = blockIdx.x * 64, n0 = blockIdx.y * 64;
    const int lr = tid >> 2;          // 0..63 row in tile
    const int lk = (tid & 3) << 2;    // 0,4,8,12
    const int tm = (tid & 15) << 2;   // m offset for compute
    const int tn = (tid >> 4) << 2;   // n offset for compute

    ull acc2[2][4];
#pragma unroll
    for (int i = 0; i < 2; i++)
#pragma unroll
        for (int j = 0; j < 4; j++) acc2[i][j] = 0ull;

    const float* Ap = A + (size_t)(m0 + lr) * DIM + lk;
    const float* Wp = W + (size_t)(n0 + lr) * DIM + lk;

    float4 av = *(const float4*)Ap;
    float4 wv = *(const float4*)Wp;

    for (int k0 = 0; k0 < DIM; k0 += 16) {
        __syncthreads();
        As[lk + 0][lr] = av.x; As[lk + 1][lr] = av.y;
        As[lk + 2][lr] = av.z; As[lk + 3][lr] = av.w;
        Ws[lk + 0][lr] = wv.x; Ws[lk + 1][lr] = wv.y;
        Ws[lk + 2][lr] = wv.z; Ws[lk + 3][lr] = wv.w;
        __syncthreads();
        if (k0 + 16 < DIM) {
            av = *(const float4*)(Ap + k0 + 16);
            wv = *(const float4*)(Wp + k0 + 16);
        }
#pragma unroll
        for (int kk = 0; kk < 16; kk++) {
            float4 a = *(const float4*)&As[kk][tm];
            float4 w = *(const float4*)&Ws[kk][tn];
            ull am0 = pack2(a.x, a.y);
            ull am1 = pack2(a.z, a.w);
            ull w0 = pack2(w.x, w.x), w1 = pack2(w.y, w.y);
            ull w2 = pack2(w.z, w.z), w3 = pack2(w.w, w.w);
            acc2[0][0] = ffma2(am0, w0, acc2[0][0]);
            acc2[0][1] = ffma2(am0, w1, acc2[0][1]);
            acc2[0][2] = ffma2(am0, w2, acc2[0][2]);
            acc2[0][3] = ffma2(am0, w3, acc2[0][3]);
            acc2[1][0] = ffma2(am1, w0, acc2[1][0]);
            acc2[1][1] = ffma2(am1, w1, acc2[1][1]);
            acc2[1][2] = ffma2(am1, w2, acc2[1][2]);
            acc2[1][3] = ffma2(am1, w3, acc2[1][3]);
        }
    }
    // unpack: acc2[i2][j] holds rows (tm+2*i2, tm+2*i2+1), col tn+j
    float accf[4][4];
#pragma unroll
    for (int i2 = 0; i2 < 2; i2++)
#pragma unroll
        for (int j = 0; j < 4; j++)
            unpack2(acc2[i2][j], accf[2 * i2][j], accf[2 * i2 + 1][j]);

    float4 bv = *(const float4*)(bias + n0 + tn);
#pragma unroll
    for (int i = 0; i < 4; i++) {
        float4 o;
        o.x = fmaxf(accf[i][0] + bv.x, 0.f);
        o.y = fmaxf(accf[i][1] + bv.y, 0.f);
        o.z = fmaxf(accf[i][2] + bv.z, 0.f);
        o.w = fmaxf(accf[i][3] + bv.w, 0.f);
        *(float4*)(C + (size_t)(m0 + tm + i) * DIM + n0 + tn) = o;
    }
}

// ---------------------------------------------------------------------------
// energy[bh, t, s] = (q[b,t,h,:] . k[b,s,h,:]) * 0.125 + eb
// p = sigmoid(energy * 5). Packed f32x2 FMA on the inner product.
// ---------------------------------------------------------------------------
__device__ __forceinline__ float sigmoid5(float e) {
    return 1.f / (1.f + __expf(-5.f * e));
}

__global__ __launch_bounds__(256) void energy_kernel(
    const float* __restrict__ ebias, float* __restrict__ p) {
    __shared__ float Qs[64][64];
    __shared__ float Ks[64][64];
    const int tid = threadIdx.x;
    const int s0 = blockIdx.x * 64;
    const int t0 = blockIdx.y * 64;
    const int bh = blockIdx.z;
    const int b = bh >> 4, h = bh & 15;

#pragma unroll
    for (int it = 0; it < 4; it++) {
        int idx = tid + it * 256;
        int row = idx >> 4;
        int c4  = (idx & 15) << 2;
        float4 qv = *(const float4*)(g_q + (size_t)(b * TGT + t0 + row) * DIM + h * DH + c4);
        Qs[c4 + 0][row] = qv.x; Qs[c4 + 1][row] = qv.y;
        Qs[c4 + 2][row] = qv.z; Qs[c4 + 3][row] = qv.w;
        float4 kv = *(const float4*)(g_k + (size_t)(b * SRC + s0 + row) * DIM + h * DH + c4);
        Ks[c4 + 0][row] = kv.x; Ks[c4 + 1][row] = kv.y;
        Ks[c4 + 2][row] = kv.z; Ks[c4 + 3][row] = kv.w;
    }
    __syncthreads();

    const int tm = (tid & 15) << 2;   // t offset
    const int tn = (tid >> 4) << 2;   // s offset
    ull acc2[2][4];
#pragma unroll
    for (int i = 0; i < 2; i++)
#pragma unroll
        for (int j = 0; j < 4; j++) acc2[i][j] = 0ull;

#pragma unroll
    for (int kk = 0; kk < 64; kk++) {
        float4 a = *(const float4*)&Qs[kk][tm];
        float4 w = *(const float4*)&Ks[kk][tn];
        ull am0 = pack2(a.x, a.y);
        ull am1 = pack2(a.z, a.w);
        ull w0 = pack2(w.x, w.x), w1 = pack2(w.y, w.y);
        ull w2 = pack2(w.z, w.z), w3 = pack2(w.w, w.w);
        acc2[0][0] = ffma2(am0, w0, acc2[0][0]);
        acc2[0][1] = ffma2(am0, w1, acc2[0][1]);
        acc2[0][2] = ffma2(am0, w2, acc2[0][2]);
        acc2[0][3] = ffma2(am0, w3, acc2[0][3]);
        acc2[1][0] = ffma2(am1, w0, acc2[1][0]);
        acc2[1][1] = ffma2(am1, w1, acc2[1][1]);
        acc2[1][2] = ffma2(am1, w2, acc2[1][2]);
        acc2[1][3] = ffma2(am1, w3, acc2[1][3]);
    }
    float accf[4][4];
#pragma unroll
    for (int i2 = 0; i2 < 2; i2++)
#pragma unroll
        for (int j = 0; j < 4; j++)
            unpack2(acc2[i2][j], accf[2 * i2][j], accf[2 * i2 + 1][j]);

    const float eb = ebias[0];
#pragma unroll
    for (int i = 0; i < 4; i++) {
        float4 o;
        o.x = sigmoid5(accf[i][0] * 0.125f + eb);
        o.y = sigmoid5(accf[i][1] * 0.125f + eb);
        o.z = sigmoid5(accf[i][2] * 0.125f + eb);
        o.w = sigmoid5(accf[i][3] * 0.125f + eb);
        *(float4*)(p + ((size_t)bh * TGT + t0 + tm + i) * SRC + s0 + tn) = o;
    }
}

// ---------------------------------------------------------------------------
// Monotonic alignment: one WARP per bh row, zero barriers.
// Per t:  c[n] = a[n]*c[n-1] + b[n],  a[n] = 1-p_t[n-1] (a[0]=0),
//         b[n] = alpha_{t-1}[n] (t=0: delta(n,0)),  alpha_t[n] = p_t[n]*c[n].
// 16 src elems per lane in registers; serial local affine scan + warp shuffle
// scan of (A,B) pairs; p[t+1] prefetched before the scan of step t.
// ---------------------------------------------------------------------------
__global__ __launch_bounds__(32) void align_kernel(
    const float* __restrict__ p, float* __restrict__ alpha) {
    const int bh = blockIdx.x;
    const int lane = threadIdx.x;
    const float* prow = p + (size_t)bh * TGT * SRC + lane * 16;
    float* arow = alpha + (size_t)bh * TGT * SRC + lane * 16;

    float4 pf0 = *(const float4*)(prow + 0);
    float4 pf1 = *(const float4*)(prow + 4);
    float4 pf2 = *(const float4*)(prow + 8);
    float4 pf3 = *(const float4*)(prow + 12);

    float b[16];
#pragma unroll
    for (int i = 0; i < 16; i++) b[i] = 0.f;
    if (lane == 0) b[0] = 1.f;

    for (int t = 0; t < TGT; t++) {
        float pv[16];
        pv[0] = pf0.x; pv[1] = pf0.y; pv[2]  = pf0.z; pv[3]  = pf0.w;
        pv[4] = pf1.x; pv[5] = pf1.y; pv[6]  = pf1.z; pv[7]  = pf1.w;
        pv[8] = pf2.x; pv[9] = pf2.y; pv[10] = pf2.z; pv[11] = pf2.w;
        pv[12] = pf3.x; pv[13] = pf3.y; pv[14] = pf3.z; pv[15] = pf3.w;

        if (t + 1 < TGT) {
            const float* np = prow + (size_t)(t + 1) * SRC;
            pf0 = *(const float4*)(np + 0);
            pf1 = *(const float4*)(np + 4);
            pf2 = *(const float4*)(np + 8);
            pf3 = *(const float4*)(np + 12);
        }

        float pm1 = __shfl_up_sync(0xffffffffu, pv[15], 1);
        float a0 = lane ? (1.f - pm1) : 0.f;

        // local affine scan with c_in = 0:  cl[i] inclusive, Ap[i] = prod a
        float Ap[16], cl[16];
        Ap[0] = a0;
        cl[0] = b[0];
#pragma unroll
        for (int i = 1; i < 16; i++) {
            float ai = 1.f - pv[i - 1];
            cl[i] = fmaf(ai, cl[i - 1], b[i]);
            Ap[i] = Ap[i - 1] * ai;
        }

        // warp inclusive scan of per-lane affine maps (A, B)
        float SA = Ap[15], SB = cl[15];
#pragma unroll
        for (int d = 1; d < 32; d <<= 1) {
            float Aq = __shfl_up_sync(0xffffffffu, SA, d);
            float Bq = __shfl_up_sync(0xffffffffu, SB, d);
            if (lane >= d) { SB = fmaf(Bq, SA, SB); SA *= Aq; }
        }
        float EB = __shfl_up_sync(0xffffffffu, SB, 1);
        float cin = lane ? EB : 0.f;   // c value entering this lane

        float o[16];
#pragma unroll
        for (int i = 0; i < 16; i++) {
            float c = fmaf(Ap[i], cin, cl[i]);
            o[i] = pv[i] * c;
            b[i] = o[i];
        }
        float4* ao = (float4*)(arow + (size_t)t * SRC);
        ao[0] = make_float4(o[0],  o[1],  o[2],  o[3]);
        ao[1] = make_float4(o[4],  o[5],  o[6],  o[7]);
        ao[2] = make_float4(o[8],  o[9],  o[10], o[11]);
        ao[3] = make_float4(o[12], o[13], o[14], o[15]);
    }
}

// ---------------------------------------------------------------------------
extern "C" void kernel_launch(void* const* d_in, const int* in_sizes, int n_in,
                              void* d_out, int out_size) {
    const float* seqs = (const float*)d_in[0];
    const float* keys = (const float*)d_in[1];
    const float* q_w  = (const float*)d_in[2];
    const float* q_b  = (const float*)d_in[3];
    const float* k_w  = (const float*)d_in[4];
    const float* k_b  = (const float*)d_in[5];
    const float* eb   = (const float*)d_in[6];

    float* out   = (float*)d_out;
    float* p     = out;                                   // (B,H,TGT,SRC)
    float* alpha = out + (size_t)NB * NH * TGT * SRC;     // (B,H,TGT,SRC)

    float *qp = nullptr, *kp = nullptr;
    cudaGetSymbolAddress((void**)&qp, g_q);
    cudaGetSymbolAddress((void**)&kp, g_k);

    // q = relu(seqs @ q_w^T + q_b): M = 8*256 = 2048
    gemm_relu_kernel<<<dim3(2048 / 64, DIM / 64), 256>>>(seqs, q_w, q_b, qp);
    // k = relu(keys @ k_w^T + k_b): M = 8*512 = 4096
    gemm_relu_kernel<<<dim3(4096 / 64, DIM / 64), 256>>>(keys, k_w, k_b, kp);
    // p_choose
    energy_kernel<<<dim3(SRC / 64, TGT / 64, NB * NH), 256>>>(eb, p);
    // alpha
    align_kernel<<<NB * NH, 32>>>(p, alpha);
}

// round 3
// speedup vs baseline: 1.1651x; 1.0084x over previous
#include <cuda_runtime.h>

#define NB   8
#define TGT  256
#define SRC  512
#define DIM  1024
#define NH   16
#define DH   64

typedef unsigned long long ull;

// scratch for projected q/k (no cudaMalloc allowed)
__device__ float g_q[(size_t)NB * TGT * DIM];   // 8 MB
__device__ float g_k[(size_t)NB * SRC * DIM];   // 16 MB

__device__ __forceinline__ ull ffma2(ull a, ull b, ull c) {
    ull d;
    asm("fma.rn.f32x2 %0, %1, %2, %3;" : "=l"(d) : "l"(a), "l"(b), "l"(c));
    return d;
}
__device__ __forceinline__ void unpack2(ull v, float& lo, float& hi) {
    asm("mov.b64 {%0, %1}, %2;" : "=f"(lo), "=f"(hi) : "l"(v));
}

// ---------------------------------------------------------------------------
// C[m,n] = relu( sum_k A[m,k]*W[n,k] + bias[n] ),  K = N = 1024
// 128x128 tile, BK=16, 256 threads, 8x8 per thread.
// M-pairs packed in f32x2 lanes; W duplicated in smem so packed W operands
// come straight from LDS (no per-iteration MOVs).
// ---------------------------------------------------------------------------
__global__ __launch_bounds__(256, 1) void gemm_relu_kernel(
    const float* __restrict__ A, const float* __restrict__ W,
    const float* __restrict__ bias, float* __restrict__ C) {
    __shared__ float As[16][128];    // [k][m]
    __shared__ float Wd[16][256];    // [k][2n] duplicated pairs

    const int tid = threadIdx.x;
    const int m0 = blockIdx.x * 128, n0 = blockIdx.y * 128;
    const int lr = tid >> 1;             // 0..127
    const int lk = (tid & 1) * 8;        // 0 or 8
    const int tm = (tid & 15) * 8;       // m offset (8 rows)
    const int tn = (tid >> 4) * 8;       // n offset (8 cols)

    ull acc[4][8];
#pragma unroll
    for (int i = 0; i < 4; i++)
#pragma unroll
        for (int j = 0; j < 8; j++) acc[i][j] = 0ull;

    const float* Ap = A + (size_t)(m0 + lr) * DIM + lk;
    const float* Wp = W + (size_t)(n0 + lr) * DIM + lk;

    float4 av0 = *(const float4*)(Ap + 0);
    float4 av1 = *(const float4*)(Ap + 4);
    float4 wv0 = *(const float4*)(Wp + 0);
    float4 wv1 = *(const float4*)(Wp + 4);

    for (int k0 = 0; k0 < DIM; k0 += 16) {
        __syncthreads();
        As[lk + 0][lr] = av0.x; As[lk + 1][lr] = av0.y;
        As[lk + 2][lr] = av0.z; As[lk + 3][lr] = av0.w;
        As[lk + 4][lr] = av1.x; As[lk + 5][lr] = av1.y;
        As[lk + 6][lr] = av1.z; As[lk + 7][lr] = av1.w;
        *(float2*)&Wd[lk + 0][2 * lr] = make_float2(wv0.x, wv0.x);
        *(float2*)&Wd[lk + 1][2 * lr] = make_float2(wv0.y, wv0.y);
        *(float2*)&Wd[lk + 2][2 * lr] = make_float2(wv0.z, wv0.z);
        *(float2*)&Wd[lk + 3][2 * lr] = make_float2(wv0.w, wv0.w);
        *(float2*)&Wd[lk + 4][2 * lr] = make_float2(wv1.x, wv1.x);
        *(float2*)&Wd[lk + 5][2 * lr] = make_float2(wv1.y, wv1.y);
        *(float2*)&Wd[lk + 6][2 * lr] = make_float2(wv1.z, wv1.z);
        *(float2*)&Wd[lk + 7][2 * lr] = make_float2(wv1.w, wv1.w);
        __syncthreads();
        if (k0 + 16 < DIM) {
            av0 = *(const float4*)(Ap + k0 + 16);
            av1 = *(const float4*)(Ap + k0 + 20);
            wv0 = *(const float4*)(Wp + k0 + 16);
            wv1 = *(const float4*)(Wp + k0 + 20);
        }
#pragma unroll
        for (int kk = 0; kk < 16; kk++) {
            ulonglong2 a0 = *(const ulonglong2*)&As[kk][tm];
            ulonglong2 a1 = *(const ulonglong2*)&As[kk][tm + 4];
            ulonglong2 w0 = *(const ulonglong2*)&Wd[kk][2 * tn + 0];
            ulonglong2 w1 = *(const ulonglong2*)&Wd[kk][2 * tn + 4];
            ulonglong2 w2 = *(const ulonglong2*)&Wd[kk][2 * tn + 8];
            ulonglong2 w3 = *(const ulonglong2*)&Wd[kk][2 * tn + 12];
            acc[0][0] = ffma2(a0.x, w0.x, acc[0][0]);
            acc[0][1] = ffma2(a0.x, w0.y, acc[0][1]);
            acc[0][2] = ffma2(a0.x, w1.x, acc[0][2]);
            acc[0][3] = ffma2(a0.x, w1.y, acc[0][3]);
            acc[0][4] = ffma2(a0.x, w2.x, acc[0][4]);
            acc[0][5] = ffma2(a0.x, w2.y, acc[0][5]);
            acc[0][6] = ffma2(a0.x, w3.x, acc[0][6]);
            acc[0][7] = ffma2(a0.x, w3.y, acc[0][7]);
            acc[1][0] = ffma2(a0.y, w0.x, acc[1][0]);
            acc[1][1] = ffma2(a0.y, w0.y, acc[1][1]);
            acc[1][2] = ffma2(a0.y, w1.x, acc[1][2]);
            acc[1][3] = ffma2(a0.y, w1.y, acc[1][3]);
            acc[1][4] = ffma2(a0.y, w2.x, acc[1][4]);
            acc[1][5] = ffma2(a0.y, w2.y, acc[1][5]);
            acc[1][6] = ffma2(a0.y, w3.x, acc[1][6]);
            acc[1][7] = ffma2(a0.y, w3.y, acc[1][7]);
            acc[2][0] = ffma2(a1.x, w0.x, acc[2][0]);
            acc[2][1] = ffma2(a1.x, w0.y, acc[2][1]);
            acc[2][2] = ffma2(a1.x, w1.x, acc[2][2]);
            acc[2][3] = ffma2(a1.x, w1.y, acc[2][3]);
            acc[2][4] = ffma2(a1.x, w2.x, acc[2][4]);
            acc[2][5] = ffma2(a1.x, w2.y, acc[2][5]);
            acc[2][6] = ffma2(a1.x, w3.x, acc[2][6]);
            acc[2][7] = ffma2(a1.x, w3.y, acc[2][7]);
            acc[3][0] = ffma2(a1.y, w0.x, acc[3][0]);
            acc[3][1] = ffma2(a1.y, w0.y, acc[3][1]);
            acc[3][2] = ffma2(a1.y, w1.x, acc[3][2]);
            acc[3][3] = ffma2(a1.y, w1.y, acc[3][3]);
            acc[3][4] = ffma2(a1.y, w2.x, acc[3][4]);
            acc[3][5] = ffma2(a1.y, w2.y, acc[3][5]);
            acc[3][6] = ffma2(a1.y, w3.x, acc[3][6]);
            acc[3][7] = ffma2(a1.y, w3.y, acc[3][7]);
        }
    }

    float4 bv0 = *(const float4*)(bias + n0 + tn);
    float4 bv1 = *(const float4*)(bias + n0 + tn + 4);
    float bb[8] = {bv0.x, bv0.y, bv0.z, bv0.w, bv1.x, bv1.y, bv1.z, bv1.w};
#pragma unroll
    for (int mi = 0; mi < 4; mi++) {
        float lo[8], hi[8];
#pragma unroll
        for (int j = 0; j < 8; j++) unpack2(acc[mi][j], lo[j], hi[j]);
        float* r0 = C + (size_t)(m0 + tm + 2 * mi) * DIM + n0 + tn;
        float* r1 = r0 + DIM;
        float4 o;
        o.x = fmaxf(lo[0] + bb[0], 0.f); o.y = fmaxf(lo[1] + bb[1], 0.f);
        o.z = fmaxf(lo[2] + bb[2], 0.f); o.w = fmaxf(lo[3] + bb[3], 0.f);
        *(float4*)r0 = o;
        o.x = fmaxf(lo[4] + bb[4], 0.f); o.y = fmaxf(lo[5] + bb[5], 0.f);
        o.z = fmaxf(lo[6] + bb[6], 0.f); o.w = fmaxf(lo[7] + bb[7], 0.f);
        *(float4*)(r0 + 4) = o;
        o.x = fmaxf(hi[0] + bb[0], 0.f); o.y = fmaxf(hi[1] + bb[1], 0.f);
        o.z = fmaxf(hi[2] + bb[2], 0.f); o.w = fmaxf(hi[3] + bb[3], 0.f);
        *(float4*)r1 = o;
        o.x = fmaxf(hi[4] + bb[4], 0.f); o.y = fmaxf(hi[5] + bb[5], 0.f);
        o.z = fmaxf(hi[6] + bb[6], 0.f); o.w = fmaxf(hi[7] + bb[7], 0.f);
        *(float4*)(r1 + 4) = o;
    }
}

// ---------------------------------------------------------------------------
// p = sigmoid((q.k * 0.125 + eb) * 5), 64x64 tile per block, f32x2 FMA,
// K duplicated in smem.
// ---------------------------------------------------------------------------
__device__ __forceinline__ float sigmoid5(float e) {
    return 1.f / (1.f + __expf(-5.f * e));
}

__global__ __launch_bounds__(256) void energy_kernel(
    const float* __restrict__ ebias, float* __restrict__ p) {
    __shared__ float Qs[64][64];      // [k][t]
    __shared__ float Kd[64][128];     // [k][2s] duplicated
    const int tid = threadIdx.x;
    const int s0 = blockIdx.x * 64;
    const int t0 = blockIdx.y * 64;
    const int bh = blockIdx.z;
    const int b = bh >> 4, h = bh & 15;

#pragma unroll
    for (int it = 0; it < 4; it++) {
        int idx = tid + it * 256;
        int row = idx >> 4;
        int c4  = (idx & 15) << 2;
        float4 qv = *(const float4*)(g_q + (size_t)(b * TGT + t0 + row) * DIM + h * DH + c4);
        Qs[c4 + 0][row] = qv.x; Qs[c4 + 1][row] = qv.y;
        Qs[c4 + 2][row] = qv.z; Qs[c4 + 3][row] = qv.w;
        float4 kv = *(const float4*)(g_k + (size_t)(b * SRC + s0 + row) * DIM + h * DH + c4);
        *(float2*)&Kd[c4 + 0][2 * row] = make_float2(kv.x, kv.x);
        *(float2*)&Kd[c4 + 1][2 * row] = make_float2(kv.y, kv.y);
        *(float2*)&Kd[c4 + 2][2 * row] = make_float2(kv.z, kv.z);
        *(float2*)&Kd[c4 + 3][2 * row] = make_float2(kv.w, kv.w);
    }
    __syncthreads();

    const int tm = (tid & 15) << 2;   // t offset (4 rows = 2 pairs)
    const int tn = (tid >> 4) << 2;   // s offset (4 cols)
    ull acc[2][4];
#pragma unroll
    for (int i = 0; i < 2; i++)
#pragma unroll
        for (int j = 0; j < 4; j++) acc[i][j] = 0ull;

#pragma unroll
    for (int kk = 0; kk < 64; kk++) {
        ulonglong2 qa = *(const ulonglong2*)&Qs[kk][tm];
        ulonglong2 k0 = *(const ulonglong2*)&Kd[kk][2 * tn + 0];
        ulonglong2 k1 = *(const ulonglong2*)&Kd[kk][2 * tn + 4];
        acc[0][0] = ffma2(qa.x, k0.x, acc[0][0]);
        acc[0][1] = ffma2(qa.x, k0.y, acc[0][1]);
        acc[0][2] = ffma2(qa.x, k1.x, acc[0][2]);
        acc[0][3] = ffma2(qa.x, k1.y, acc[0][3]);
        acc[1][0] = ffma2(qa.y, k0.x, acc[1][0]);
        acc[1][1] = ffma2(qa.y, k0.y, acc[1][1]);
        acc[1][2] = ffma2(qa.y, k1.x, acc[1][2]);
        acc[1][3] = ffma2(qa.y, k1.y, acc[1][3]);
    }
    const float eb = ebias[0];
#pragma unroll
    for (int i2 = 0; i2 < 2; i2++) {
        float lo[4], hi[4];
#pragma unroll
        for (int j = 0; j < 4; j++) unpack2(acc[i2][j], lo[j], hi[j]);
        float* r0 = p + ((size_t)bh * TGT + t0 + tm + 2 * i2) * SRC + s0 + tn;
        float4 o;
        o.x = sigmoid5(lo[0] * 0.125f + eb); o.y = sigmoid5(lo[1] * 0.125f + eb);
        o.z = sigmoid5(lo[2] * 0.125f + eb); o.w = sigmoid5(lo[3] * 0.125f + eb);
        *(float4*)r0 = o;
        o.x = sigmoid5(hi[0] * 0.125f + eb); o.y = sigmoid5(hi[1] * 0.125f + eb);
        o.z = sigmoid5(hi[2] * 0.125f + eb); o.w = sigmoid5(hi[3] * 0.125f + eb);
        *(float4*)(r0 + SRC) = o;
    }
}

// ---------------------------------------------------------------------------
// Monotonic alignment: one WARP per bh, TWO t-steps per warp scan, branchless.
// State (x,y) = (c_t, c_{t+1}) obeys v[n] = M[n] v[n-1] + u[n] with
// lower-triangular M = [[at,0],[pt*at, at1]], u = (b[n], pt[n]*b[n]).
// Affine warp scan over (p00,p10,p11,X,Y).
// ---------------------------------------------------------------------------
__global__ __launch_bounds__(32) void align_kernel(
    const float* __restrict__ p, float* __restrict__ alpha) {
    const int bh = blockIdx.x;
    const int lane = threadIdx.x;
    const float* prow = p + (size_t)bh * TGT * SRC + lane * 16;
    float* arow = alpha + (size_t)bh * TGT * SRC + lane * 16;

    float b[16];
#pragma unroll
    for (int i = 0; i < 16; i++) b[i] = 0.f;
    if (lane == 0) b[0] = 1.f;

    float4 f[8];
#pragma unroll
    for (int j = 0; j < 4; j++) {
        f[j]     = *(const float4*)(prow + 0 * SRC + 4 * j);
        f[4 + j] = *(const float4*)(prow + 1 * SRC + 4 * j);
    }

    for (int tp = 0; tp < TGT / 2; tp++) {
        float pt[16], pt1[16];
#pragma unroll
        for (int j = 0; j < 4; j++) {
            pt[4 * j + 0] = f[j].x;  pt[4 * j + 1] = f[j].y;
            pt[4 * j + 2] = f[j].z;  pt[4 * j + 3] = f[j].w;
            pt1[4 * j + 0] = f[4 + j].x; pt1[4 * j + 1] = f[4 + j].y;
            pt1[4 * j + 2] = f[4 + j].z; pt1[4 * j + 3] = f[4 + j].w;
        }
        if (tp + 1 < TGT / 2) {
            const float* np = prow + (size_t)(2 * tp + 2) * SRC;
#pragma unroll
            for (int j = 0; j < 4; j++) {
                f[j]     = *(const float4*)(np + 4 * j);
                f[4 + j] = *(const float4*)(np + SRC + 4 * j);
            }
        }

        float ptm  = __shfl_up_sync(0xffffffffu, pt[15], 1);
        float pt1m = __shfl_up_sync(0xffffffffu, pt1[15], 1);
        float at_first  = lane ? (1.f - ptm)  : 0.f;
        float at1_first = lane ? (1.f - pt1m) : 0.f;

        // local scan: inclusive locals (xl,yl) with zero input + cumulative P
        float p00[16], p10[16], p11[16], xl[16], yl[16];
        float x = 0.f, y = 0.f, c00 = 1.f, c10 = 0.f, c11 = 1.f;
#pragma unroll
        for (int i = 0; i < 16; i++) {
            float at  = (i == 0) ? at_first  : (1.f - pt[i - 1]);
            float at1 = (i == 0) ? at1_first : (1.f - pt1[i - 1]);
            x = fmaf(at, x, b[i]);
            y = fmaf(at1, y, pt[i] * x);
            float n00 = at * c00;
            float n10 = fmaf(pt[i] * at, c00, at1 * c10);
            float n11 = at1 * c11;
            c00 = n00; c10 = n10; c11 = n11;
            p00[i] = c00; p10[i] = c10; p11[i] = c11;
            xl[i] = x; yl[i] = y;
        }

        // warp inclusive scan of affine maps (P, V), branchless
        float s00 = c00, s10 = c10, s11 = c11, X = x, Y = y;
#pragma unroll
        for (int d = 1; d < 32; d <<= 1) {
            float g00 = __shfl_up_sync(0xffffffffu, s00, d);
            float g10 = __shfl_up_sync(0xffffffffu, s10, d);
            float g11 = __shfl_up_sync(0xffffffffu, s11, d);
            float gX  = __shfl_up_sync(0xffffffffu, X, d);
            float gY  = __shfl_up_sync(0xffffffffu, Y, d);
            bool use = (lane >= d);
            float nX  = fmaf(s00, gX, X);
            float nY  = fmaf(s10, gX, fmaf(s11, gY, Y));
            float n00 = s00 * g00;
            float n10 = fmaf(s10, g00, s11 * g10);
            float n11 = s11 * g11;
            X = use ? nX : X;   Y = use ? nY : Y;
            s00 = use ? n00 : s00; s10 = use ? n10 : s10; s11 = use ? n11 : s11;
        }
        float Xin = __shfl_up_sync(0xffffffffu, X, 1);
        float Yin = __shfl_up_sync(0xffffffffu, Y, 1);
        Xin = lane ? Xin : 0.f;
        Yin = lane ? Yin : 0.f;

        float ot[16];
#pragma unroll
        for (int i = 0; i < 16; i++) {
            float xv = fmaf(p00[i], Xin, xl[i]);
            float yv = fmaf(p10[i], Xin, fmaf(p11[i], Yin, yl[i]));
            ot[i] = pt[i] * xv;
            b[i] = pt1[i] * yv;     // alpha_{t+1} = next b
        }
        float* a0 = arow + (size_t)(2 * tp) * SRC;
        float* a1 = a0 + SRC;
#pragma unroll
        for (int j = 0; j < 4; j++) {
            *(float4*)(a0 + 4 * j) = make_float4(ot[4 * j], ot[4 * j + 1], ot[4 * j + 2], ot[4 * j + 3]);
            *(float4*)(a1 + 4 * j) = make_float4(b[4 * j], b[4 * j + 1], b[4 * j + 2], b[4 * j + 3]);
        }
    }
}

// ---------------------------------------------------------------------------
extern "C" void kernel_launch(void* const* d_in, const int* in_sizes, int n_in,
                              void* d_out, int out_size) {
    const float* seqs = (const float*)d_in[0];
    const float* keys = (const float*)d_in[1];
    const float* q_w  = (const float*)d_in[2];
    const float* q_b  = (const float*)d_in[3];
    const float* k_w  = (const float*)d_in[4];
    const float* k_b  = (const float*)d_in[5];
    const float* eb   = (const float*)d_in[6];

    float* out   = (float*)d_out;
    float* p     = out;                                   // (B,H,TGT,SRC)
    float* alpha = out + (size_t)NB * NH * TGT * SRC;     // (B,H,TGT,SRC)

    float *qp = nullptr, *kp = nullptr;
    cudaGetSymbolAddress((void**)&qp, g_q);
    cudaGetSymbolAddress((void**)&kp, g_k);

    // q = relu(seqs @ q_w^T + q_b): M = 8*256 = 2048
    gemm_relu_kernel<<<dim3(2048 / 128, DIM / 128), 256>>>(seqs, q_w, q_b, qp);
    // k = relu(keys @ k_w^T + k_b): M = 8*512 = 4096
    gemm_relu_kernel<<<dim3(4096 / 128, DIM / 128), 256>>>(keys, k_w, k_b, kp);
    // p_choose
    energy_kernel<<<dim3(SRC / 64, TGT / 64, NB * NH), 256>>>(eb, p);
    // alpha
    align_kernel<<<NB * NH, 32>>>(p, alpha);
}

// round 5
// speedup vs baseline: 2.7049x; 2.3217x over previous
#include <cuda_runtime.h>
#include <cuda_bf16.h>
#include <cstdint>

#define NB   8
#define TGT  256
#define SRC  512
#define DIM  1024
#define NH   16
#define DH   64

typedef unsigned int u32;
typedef unsigned long long u64;

// ---------------- device scratch (no cudaMalloc allowed) --------------------
__device__ __nv_bfloat16 g_seq_hi[(size_t)NB * TGT * DIM];
__device__ __nv_bfloat16 g_seq_lo[(size_t)NB * TGT * DIM];
__device__ __nv_bfloat16 g_key_hi[(size_t)NB * SRC * DIM];
__device__ __nv_bfloat16 g_key_lo[(size_t)NB * SRC * DIM];
__device__ __nv_bfloat16 g_qw_hi[(size_t)DIM * DIM];
__device__ __nv_bfloat16 g_qw_lo[(size_t)DIM * DIM];
__device__ __nv_bfloat16 g_kw_hi[(size_t)DIM * DIM];
__device__ __nv_bfloat16 g_kw_lo[(size_t)DIM * DIM];
__device__ __nv_bfloat16 g_q_hi[(size_t)NB * TGT * DIM];
__device__ __nv_bfloat16 g_q_lo[(size_t)NB * TGT * DIM];
__device__ __nv_bfloat16 g_k_hi[(size_t)NB * SRC * DIM];
__device__ __nv_bfloat16 g_k_lo[(size_t)NB * SRC * DIM];

// ---------------- PTX helpers -----------------------------------------------
__device__ __forceinline__ u32 smem_u32(const void* p) {
    u32 a;
    asm("{ .reg .u64 t; cvta.to.shared.u64 t, %1; cvt.u32.u64 %0, t; }"
        : "=r"(a) : "l"(p));
    return a;
}

__device__ __forceinline__ u32 swz(u32 off) { return off ^ ((off >> 3) & 0x70); }

#define CP_ASYNC16(dst, src) \
    asm volatile("cp.async.cg.shared.global [%0], [%1], 16;" \
                 :: "r"(dst), "l"(src) : "memory")
#define CP_COMMIT() asm volatile("cp.async.commit_group;" ::: "memory")
#define CP_WAIT(n)  asm volatile("cp.async.wait_group %0;" :: "n"(n) : "memory")

__device__ __forceinline__ void ldsm4(u32& r0, u32& r1, u32& r2, u32& r3, u32 addr) {
    asm volatile("ldmatrix.sync.aligned.m8n8.x4.shared.b16 {%0,%1,%2,%3}, [%4];"
                 : "=r"(r0), "=r"(r1), "=r"(r2), "=r"(r3) : "r"(addr));
}

__device__ __forceinline__ void mma16816(float* c, const u32* a, const u32* b) {
    asm volatile(
        "mma.sync.aligned.m16n8k16.row.col.f32.bf16.bf16.f32 "
        "{%0,%1,%2,%3}, {%4,%5,%6,%7}, {%8,%9}, {%0,%1,%2,%3};"
        : "+f"(c[0]), "+f"(c[1]), "+f"(c[2]), "+f"(c[3])
        : "r"(a[0]), "r"(a[1]), "r"(a[2]), "r"(a[3]), "r"(b[0]), "r"(b[1]));
}

// ---------------------------------------------------------------------------
// fp32 -> (hi, lo) bf16 split
// ---------------------------------------------------------------------------
__global__ __launch_bounds__(256) void split_kernel(
    const float* __restrict__ x, __nv_bfloat16* __restrict__ hi,
    __nv_bfloat16* __restrict__ lo, int n4) {
    int i = blockIdx.x * 256 + threadIdx.x;
    if (i >= n4) return;
    float4 v = ((const float4*)x)[i];
    __nv_bfloat16 h[4], l[4];
    h[0] = __float2bfloat16(v.x); l[0] = __float2bfloat16(v.x - __bfloat162float(h[0]));
    h[1] = __float2bfloat16(v.y); l[1] = __float2bfloat16(v.y - __bfloat162float(h[1]));
    h[2] = __float2bfloat16(v.z); l[2] = __float2bfloat16(v.z - __bfloat162float(h[2]));
    h[3] = __float2bfloat16(v.w); l[3] = __float2bfloat16(v.w - __bfloat162float(h[3]));
    ((uint2*)hi)[i] = *(uint2*)h;
    ((uint2*)lo)[i] = *(uint2*)l;
}

// ---------------------------------------------------------------------------
// Projection: C = relu(A @ W^T + bias), split-bf16 via HMMA m16n8k16.
// Virtual K = 3*1024 (segments: hi*hi, hi*lo, lo*hi). 128x128 CTA tile,
// 8 warps (warp tile 32x64), BK=64, cp.async 2-stage pipeline, SW128 smem.
// ---------------------------------------------------------------------------
#define PROJ_SMEM (1024 + 2 * 32768)

__global__ __launch_bounds__(256, 2) void proj_kernel(
    const __nv_bfloat16* __restrict__ Ahi, const __nv_bfloat16* __restrict__ Alo,
    const __nv_bfloat16* __restrict__ Whi, const __nv_bfloat16* __restrict__ Wlo,
    const float* __restrict__ bias,
    __nv_bfloat16* __restrict__ Chi, __nv_bfloat16* __restrict__ Clo) {
    extern __shared__ char smraw[];
    u32 braw = smem_u32(smraw);
    u32 base = (braw + 1023) & ~1023u;

    const int tid = threadIdx.x, lane = tid & 31, wid = tid >> 5;
    const int m0 = blockIdx.x * 128, n0 = blockIdx.y * 128;
    const int wm0 = (wid >> 1) * 32, wn0 = (wid & 1) * 64;

    const __nv_bfloat16* segA[3] = {Ahi, Ahi, Alo};
    const __nv_bfloat16* segB[3] = {Whi, Wlo, Whi};

    const int r0l = tid >> 3, grp = tid & 7;   // load indices

    auto load_chunk = [&](int c, int st) {
        int seg = c >> 4;
        int k0 = (c & 15) * 64;
        const __nv_bfloat16* As = segA[seg];
        const __nv_bfloat16* Bs = segB[seg];
        u32 Ab = base + (u32)st * 32768u;
        u32 Bb = Ab + 16384u;
#pragma unroll
        for (int g = 0; g < 4; g++) {
            int row = r0l + g * 32;
            u32 d = swz((u32)(row * 128 + grp * 16));
            CP_ASYNC16(Ab + d, As + (size_t)(m0 + row) * DIM + k0 + grp * 8);
            CP_ASYNC16(Bb + d, Bs + (size_t)(n0 + row) * DIM + k0 + grp * 8);
        }
        CP_COMMIT();
    };

    load_chunk(0, 0);
    load_chunk(1, 1);

    float acc[2][8][4];
#pragma unroll
    for (int i = 0; i < 2; i++)
#pragma unroll
        for (int j = 0; j < 8; j++)
#pragma unroll
            for (int q = 0; q < 4; q++) acc[i][j][q] = 0.f;

    const int lrA = wm0 + (lane & 15);
    const int lrB = wn0 + (lane & 15);
    const u32 khi = (u32)((lane >> 4) << 4);

    for (int c = 0; c < 48; c++) {
        const int st = c & 1;
        CP_WAIT(1);
        __syncthreads();
        u32 Ab = base + (u32)st * 32768u;
        u32 Bb = Ab + 16384u;
#pragma unroll
        for (int kk = 0; kk < 4; kk++) {
            u32 kb = (u32)(kk * 32) + khi;
            u32 a0[4], a1[4];
            ldsm4(a0[0], a0[1], a0[2], a0[3], Ab + swz((u32)(lrA * 128) + kb));
            ldsm4(a1[0], a1[1], a1[2], a1[3], Ab + swz((u32)((lrA + 16) * 128) + kb));
            u32 b[8][2];
#pragma unroll
            for (int nn = 0; nn < 4; nn++) {
                u32 t0, t1, t2, t3;
                ldsm4(t0, t1, t2, t3, Bb + swz((u32)((lrB + nn * 16) * 128) + kb));
                b[2 * nn][0] = t0; b[2 * nn + 1][0] = t1;
                b[2 * nn][1] = t2; b[2 * nn + 1][1] = t3;
            }
#pragma unroll
            for (int ni = 0; ni < 8; ni++) {
                mma16816(acc[0][ni], a0, b[ni]);
                mma16816(acc[1][ni], a1, b[ni]);
            }
        }
        __syncthreads();
        if (c + 2 < 48) load_chunk(c + 2, st);
    }

    // epilogue: bias + relu + re-split to bf16 hi/lo
    const int g = lane >> 2, tg = lane & 3;
#pragma unroll
    for (int ni = 0; ni < 8; ni++) {
        int n = n0 + wn0 + ni * 8 + 2 * tg;
        float b0 = bias[n], b1 = bias[n + 1];
#pragma unroll
        for (int mi = 0; mi < 2; mi++) {
#pragma unroll
            for (int half = 0; half < 2; half++) {
                int m = m0 + wm0 + mi * 16 + half * 8 + g;
                float v0 = fmaxf(acc[mi][ni][half * 2 + 0] + b0, 0.f);
                float v1 = fmaxf(acc[mi][ni][half * 2 + 1] + b1, 0.f);
                __nv_bfloat16 h0 = __float2bfloat16(v0);
                __nv_bfloat16 h1 = __float2bfloat16(v1);
                __nv_bfloat16 l0 = __float2bfloat16(v0 - __bfloat162float(h0));
                __nv_bfloat16 l1 = __float2bfloat16(v1 - __bfloat162float(h1));
                __nv_bfloat162 hp; hp.x = h0; hp.y = h1;
                __nv_bfloat162 lp; lp.x = l0; lp.y = l1;
                *(__nv_bfloat162*)(Chi + (size_t)m * DIM + n) = hp;
                *(__nv_bfloat162*)(Clo + (size_t)m * DIM + n) = lp;
            }
        }
    }
}

// ---------------------------------------------------------------------------
// Energy: p[bh,t,s] = sigmoid(5*(q.k*0.125 + eb)), split-bf16 HMMA.
// 128x128 tile, K = 3 segments x 64, all loaded upfront (3 stages).
// ---------------------------------------------------------------------------
#define EN_SMEM (1024 + 3 * 32768)

__device__ __forceinline__ float sigmoid5(float e) {
    return 1.f / (1.f + __expf(-5.f * e));
}

__global__ __launch_bounds__(256, 2) void energy_kernel(
    const __nv_bfloat16* __restrict__ qhi, const __nv_bfloat16* __restrict__ qlo,
    const __nv_bfloat16* __restrict__ khi, const __nv_bfloat16* __restrict__ klo,
    const float* __restrict__ ebias, float* __restrict__ p) {
    extern __shared__ char smraw[];
    u32 braw = smem_u32(smraw);
    u32 base = (braw + 1023) & ~1023u;

    const int tid = threadIdx.x, lane = tid & 31, wid = tid >> 5;
    const int s0 = blockIdx.x * 128, t0 = blockIdx.y * 128;
    const int bh = blockIdx.z;
    const int b = bh >> 4, h = bh & 15;
    const int wm0 = (wid >> 1) * 32, wn0 = (wid & 1) * 64;

    const __nv_bfloat16* segQ[3] = {qhi, qhi, qlo};
    const __nv_bfloat16* segK[3] = {khi, klo, khi};

    const int r0l = tid >> 3, grp = tid & 7;

#pragma unroll
    for (int c = 0; c < 3; c++) {
        const __nv_bfloat16* Qs = segQ[c];
        const __nv_bfloat16* Ks = segK[c];
        u32 Qb = base + (u32)c * 32768u;
        u32 Kb = Qb + 16384u;
#pragma unroll
        for (int g = 0; g < 4; g++) {
            int row = r0l + g * 32;
            u32 d = swz((u32)(row * 128 + grp * 16));
            CP_ASYNC16(Qb + d, Qs + (size_t)(b * TGT + t0 + row) * DIM + h * DH + grp * 8);
            CP_ASYNC16(Kb + d, Ks + (size_t)(b * SRC + s0 + row) * DIM + h * DH + grp * 8);
        }
        CP_COMMIT();
    }
    CP_WAIT(0);
    __syncthreads();

    float acc[2][8][4];
#pragma unroll
    for (int i = 0; i < 2; i++)
#pragma unroll
        for (int j = 0; j < 8; j++)
#pragma unroll
            for (int q = 0; q < 4; q++) acc[i][j][q] = 0.f;

    const int lrA = wm0 + (lane & 15);
    const int lrB = wn0 + (lane & 15);
    const u32 khi_off = (u32)((lane >> 4) << 4);

#pragma unroll
    for (int c = 0; c < 3; c++) {
        u32 Qb = base + (u32)c * 32768u;
        u32 Kb = Qb + 16384u;
#pragma unroll
        for (int kk = 0; kk < 4; kk++) {
            u32 kb = (u32)(kk * 32) + khi_off;
            u32 a0[4], a1[4];
            ldsm4(a0[0], a0[1], a0[2], a0[3], Qb + swz((u32)(lrA * 128) + kb));
            ldsm4(a1[0], a1[1], a1[2], a1[3], Qb + swz((u32)((lrA + 16) * 128) + kb));
            u32 bb[8][2];
#pragma unroll
            for (int nn = 0; nn < 4; nn++) {
                u32 t0r, t1r, t2r, t3r;
                ldsm4(t0r, t1r, t2r, t3r, Kb + swz((u32)((lrB + nn * 16) * 128) + kb));
                bb[2 * nn][0] = t0r; bb[2 * nn + 1][0] = t1r;
                bb[2 * nn][1] = t2r; bb[2 * nn + 1][1] = t3r;
            }
#pragma unroll
            for (int ni = 0; ni < 8; ni++) {
                mma16816(acc[0][ni], a0, bb[ni]);
                mma16816(acc[1][ni], a1, bb[ni]);
            }
        }
    }

    const float eb = ebias[0];
    const int g = lane >> 2, tg = lane & 3;
#pragma unroll
    for (int ni = 0; ni < 8; ni++) {
        int s = s0 + wn0 + ni * 8 + 2 * tg;
#pragma unroll
        for (int mi = 0; mi < 2; mi++) {
#pragma unroll
            for (int half = 0; half < 2; half++) {
                int t = t0 + wm0 + mi * 16 + half * 8 + g;
                float2 o;
                o.x = sigmoid5(acc[mi][ni][half * 2 + 0] * 0.125f + eb);
                o.y = sigmoid5(acc[mi][ni][half * 2 + 1] * 0.125f + eb);
                *(float2*)(p + ((size_t)bh * TGT + t) * SRC + s) = o;
            }
        }
    }
}

// ---------------------------------------------------------------------------
// Monotonic alignment: one WARP per bh, TWO t-steps per warp scan, branchless.
// ---------------------------------------------------------------------------
__global__ __launch_bounds__(32) void align_kernel(
    const float* __restrict__ p, float* __restrict__ alpha) {
    const int bh = blockIdx.x;
    const int lane = threadIdx.x;
    const float* prow = p + (size_t)bh * TGT * SRC + lane * 16;
    float* arow = alpha + (size_t)bh * TGT * SRC + lane * 16;

    float b[16];
#pragma unroll
    for (int i = 0; i < 16; i++) b[i] = 0.f;
    if (lane == 0) b[0] = 1.f;

    float4 f[8];
#pragma unroll
    for (int j = 0; j < 4; j++) {
        f[j]     = *(const float4*)(prow + 0 * SRC + 4 * j);
        f[4 + j] = *(const float4*)(prow + 1 * SRC + 4 * j);
    }

    for (int tp = 0; tp < TGT / 2; tp++) {
        float pt[16], pt1[16];
#pragma unroll
        for (int j = 0; j < 4; j++) {
            pt[4 * j + 0] = f[j].x;  pt[4 * j + 1] = f[j].y;
            pt[4 * j + 2] = f[j].z;  pt[4 * j + 3] = f[j].w;
            pt1[4 * j + 0] = f[4 + j].x; pt1[4 * j + 1] = f[4 + j].y;
            pt1[4 * j + 2] = f[4 + j].z; pt1[4 * j + 3] = f[4 + j].w;
        }
        if (tp + 1 < TGT / 2) {
            const float* np = prow + (size_t)(2 * tp + 2) * SRC;
#pragma unroll
            for (int j = 0; j < 4; j++) {
                f[j]     = *(const float4*)(np + 4 * j);
                f[4 + j] = *(const float4*)(np + SRC + 4 * j);
            }
        }

        float ptm  = __shfl_up_sync(0xffffffffu, pt[15], 1);
        float pt1m = __shfl_up_sync(0xffffffffu, pt1[15], 1);
        float at_first  = lane ? (1.f - ptm)  : 0.f;
        float at1_first = lane ? (1.f - pt1m) : 0.f;

        float p00[16], p10[16], p11[16], xl[16], yl[16];
        float x = 0.f, y = 0.f, c00 = 1.f, c10 = 0.f, c11 = 1.f;
#pragma unroll
        for (int i = 0; i < 16; i++) {
            float at  = (i == 0) ? at_first  : (1.f - pt[i - 1]);
            float at1 = (i == 0) ? at1_first : (1.f - pt1[i - 1]);
            x = fmaf(at, x, b[i]);
            y = fmaf(at1, y, pt[i] * x);
            float n00 = at * c00;
            float n10 = fmaf(pt[i] * at, c00, at1 * c10);
            float n11 = at1 * c11;
            c00 = n00; c10 = n10; c11 = n11;
            p00[i] = c00; p10[i] = c10; p11[i] = c11;
            xl[i] = x; yl[i] = y;
        }

        float s00 = c00, s10 = c10, s11 = c11, X = x, Y = y;
#pragma unroll
        for (int d = 1; d < 32; d <<= 1) {
            float g00 = __shfl_up_sync(0xffffffffu, s00, d);
            float g10 = __shfl_up_sync(0xffffffffu, s10, d);
            float g11 = __shfl_up_sync(0xffffffffu, s11, d);
            float gX  = __shfl_up_sync(0xffffffffu, X, d);
            float gY  = __shfl_up_sync(0xffffffffu, Y, d);
            bool use = (lane >= d);
            float nX  = fmaf(s00, gX, X);
            float nY  = fmaf(s10, gX, fmaf(s11, gY, Y));
            float n00 = s00 * g00;
            float n10 = fmaf(s10, g00, s11 * g10);
            float n11 = s11 * g11;
            X = use ? nX : X;   Y = use ? nY : Y;
            s00 = use ? n00 : s00; s10 = use ? n10 : s10; s11 = use ? n11 : s11;
        }
        float Xin = __shfl_up_sync(0xffffffffu, X, 1);
        float Yin = __shfl_up_sync(0xffffffffu, Y, 1);
        Xin = lane ? Xin : 0.f;
        Yin = lane ? Yin : 0.f;

        float ot[16];
#pragma unroll
        for (int i = 0; i < 16; i++) {
            float xv = fmaf(p00[i], Xin, xl[i]);
            float yv = fmaf(p10[i], Xin, fmaf(p11[i], Yin, yl[i]));
            ot[i] = pt[i] * xv;
            b[i] = pt1[i] * yv;
        }
        float* a0 = arow + (size_t)(2 * tp) * SRC;
        float* a1 = a0 + SRC;
#pragma unroll
        for (int j = 0; j < 4; j++) {
            *(float4*)(a0 + 4 * j) = make_float4(ot[4 * j], ot[4 * j + 1], ot[4 * j + 2], ot[4 * j + 3]);
            *(float4*)(a1 + 4 * j) = make_float4(b[4 * j], b[4 * j + 1], b[4 * j + 2], b[4 * j + 3]);
        }
    }
}

// ---------------------------------------------------------------------------
extern "C" void kernel_launch(void* const* d_in, const int* in_sizes, int n_in,
                              void* d_out, int out_size) {
    const float* seqs = (const float*)d_in[0];
    const float* keys = (const float*)d_in[1];
    const float* q_w  = (const float*)d_in[2];
    const float* q_b  = (const float*)d_in[3];
    const float* k_w  = (const float*)d_in[4];
    const float* k_b  = (const float*)d_in[5];
    const float* eb   = (const float*)d_in[6];

    float* out   = (float*)d_out;
    float* p     = out;
    float* alpha = out + (size_t)NB * NH * TGT * SRC;

    __nv_bfloat16 *seq_hi, *seq_lo, *key_hi, *key_lo, *qw_hi, *qw_lo, *kw_hi, *kw_lo;
    __nv_bfloat16 *q_hi, *q_lo, *k_hi, *k_lo;
    cudaGetSymbolAddress((void**)&seq_hi, g_seq_hi);
    cudaGetSymbolAddress((void**)&seq_lo, g_seq_lo);
    cudaGetSymbolAddress((void**)&key_hi, g_key_hi);
    cudaGetSymbolAddress((void**)&key_lo, g_key_lo);
    cudaGetSymbolAddress((void**)&qw_hi, g_qw_hi);
    cudaGetSymbolAddress((void**)&qw_lo, g_qw_lo);
    cudaGetSymbolAddress((void**)&kw_hi, g_kw_hi);
    cudaGetSymbolAddress((void**)&kw_lo, g_kw_lo);
    cudaGetSymbolAddress((void**)&q_hi, g_q_hi);
    cudaGetSymbolAddress((void**)&q_lo, g_q_lo);
    cudaGetSymbolAddress((void**)&k_hi, g_k_hi);
    cudaGetSymbolAddress((void**)&k_lo, g_k_lo);

    cudaFuncSetAttribute(proj_kernel, cudaFuncAttributeMaxDynamicSharedMemorySize, PROJ_SMEM);
    cudaFuncSetAttribute(energy_kernel, cudaFuncAttributeMaxDynamicSharedMemorySize, EN_SMEM);

    // fp32 -> bf16 hi/lo splits
    {
        int n4 = NB * TGT * DIM / 4;
        split_kernel<<<(n4 + 255) / 256, 256>>>(seqs, seq_hi, seq_lo, n4);
        n4 = NB * SRC * DIM / 4;
        split_kernel<<<(n4 + 255) / 256, 256>>>(keys, key_hi, key_lo, n4);
        n4 = DIM * DIM / 4;
        split_kernel<<<(n4 + 255) / 256, 256>>>(q_w, qw_hi, qw_lo, n4);
        split_kernel<<<(n4 + 255) / 256, 256>>>(k_w, kw_hi, kw_lo, n4);
    }

    // projections (HMMA): q = relu(seqs@q_w^T+q_b), k = relu(keys@k_w^T+k_b)
    proj_kernel<<<dim3(NB * TGT / 128, DIM / 128), 256, PROJ_SMEM>>>(
        seq_hi, seq_lo, qw_hi, qw_lo, q_b, q_hi, q_lo);
    proj_kernel<<<dim3(NB * SRC / 128, DIM / 128), 256, PROJ_SMEM>>>(
        key_hi, key_lo, kw_hi, kw_lo, k_b, k_hi, k_lo);

    // p_choose (HMMA)
    energy_kernel<<<dim3(SRC / 128, TGT / 128, NB * NH), 256, EN_SMEM>>>(
        q_hi, q_lo, k_hi, k_lo, eb, p);

    // alpha
    align_kernel<<<NB * NH, 32>>>(p, alpha);
}

// round 6
// speedup vs baseline: 2.7457x; 1.0151x over previous
#include <cuda_runtime.h>
#include <cuda_bf16.h>
#include <cstdint>

#define NB   8
#define TGT  256
#define SRC  512
#define DIM  1024
#define NH   16
#define DH   64

typedef unsigned int u32;
typedef unsigned long long u64;

// ---------------- device scratch (no cudaMalloc allowed) --------------------
__device__ __nv_bfloat16 g_seq_hi[(size_t)NB * TGT * DIM];
__device__ __nv_bfloat16 g_seq_lo[(size_t)NB * TGT * DIM];
__device__ __nv_bfloat16 g_key_hi[(size_t)NB * SRC * DIM];
__device__ __nv_bfloat16 g_key_lo[(size_t)NB * SRC * DIM];
__device__ __nv_bfloat16 g_qw_hi[(size_t)DIM * DIM];
__device__ __nv_bfloat16 g_qw_lo[(size_t)DIM * DIM];
__device__ __nv_bfloat16 g_kw_hi[(size_t)DIM * DIM];
__device__ __nv_bfloat16 g_kw_lo[(size_t)DIM * DIM];
__device__ __nv_bfloat16 g_q_hi[(size_t)NB * TGT * DIM];
__device__ __nv_bfloat16 g_q_lo[(size_t)NB * TGT * DIM];
__device__ __nv_bfloat16 g_k_hi[(size_t)NB * SRC * DIM];
__device__ __nv_bfloat16 g_k_lo[(size_t)NB * SRC * DIM];

// ---------------- PTX helpers -----------------------------------------------
__device__ __forceinline__ u32 smem_u32(const void* p) {
    u32 a;
    asm("{ .reg .u64 t; cvta.to.shared.u64 t, %1; cvt.u32.u64 %0, t; }"
        : "=r"(a) : "l"(p));
    return a;
}

__device__ __forceinline__ u32 swz(u32 off) { return off ^ ((off >> 3) & 0x70); }

#define CP_ASYNC16(dst, src) \
    asm volatile("cp.async.cg.shared.global [%0], [%1], 16;" \
                 :: "r"(dst), "l"(src) : "memory")
#define CP_COMMIT() asm volatile("cp.async.commit_group;" ::: "memory")
#define CP_WAIT(n)  asm volatile("cp.async.wait_group %0;" :: "n"(n) : "memory")

__device__ __forceinline__ void ldsm4(u32& r0, u32& r1, u32& r2, u32& r3, u32 addr) {
    asm volatile("ldmatrix.sync.aligned.m8n8.x4.shared.b16 {%0,%1,%2,%3}, [%4];"
                 : "=r"(r0), "=r"(r1), "=r"(r2), "=r"(r3) : "r"(addr));
}

__device__ __forceinline__ void mma16816(float* c, const u32* a, const u32* b) {
    asm volatile(
        "mma.sync.aligned.m16n8k16.row.col.f32.bf16.bf16.f32 "
        "{%0,%1,%2,%3}, {%4,%5,%6,%7}, {%8,%9}, {%0,%1,%2,%3};"
        : "+f"(c[0]), "+f"(c[1]), "+f"(c[2]), "+f"(c[3])
        : "r"(a[0]), "r"(a[1]), "r"(a[2]), "r"(a[3]), "r"(b[0]), "r"(b[1]));
}

// ---------------------------------------------------------------------------
// Fused fp32 -> (hi, lo) bf16 split for all four inputs in ONE launch.
// float4 index ranges: [0,512K) seqs | [512K,1536K) keys | +256K qw | +256K kw
// ---------------------------------------------------------------------------
#define N4_SEQ  (NB * TGT * DIM / 4)          // 524288
#define N4_KEY  (NB * SRC * DIM / 4)          // 1048576
#define N4_W    (DIM * DIM / 4)               // 262144
#define N4_TOT  (N4_SEQ + N4_KEY + 2 * N4_W)  // 2097152

__global__ __launch_bounds__(256) void split_all_kernel(
    const float* __restrict__ seqs, const float* __restrict__ keys,
    const float* __restrict__ qw, const float* __restrict__ kw) {
    int i = blockIdx.x * 256 + threadIdx.x;
    if (i >= N4_TOT) return;
    const float* src;
    __nv_bfloat16 *hi, *lo;
    int j = i;
    if (j < N4_SEQ) {
        src = seqs; hi = g_seq_hi; lo = g_seq_lo;
    } else if ((j -= N4_SEQ) < N4_KEY) {
        src = keys; hi = g_key_hi; lo = g_key_lo;
    } else if ((j -= N4_KEY) < N4_W) {
        src = qw; hi = g_qw_hi; lo = g_qw_lo;
    } else {
        j -= N4_W;
        src = kw; hi = g_kw_hi; lo = g_kw_lo;
    }
    float4 v = ((const float4*)src)[j];
    __nv_bfloat16 h[4], l[4];
    h[0] = __float2bfloat16(v.x); l[0] = __float2bfloat16(v.x - __bfloat162float(h[0]));
    h[1] = __float2bfloat16(v.y); l[1] = __float2bfloat16(v.y - __bfloat162float(h[1]));
    h[2] = __float2bfloat16(v.z); l[2] = __float2bfloat16(v.z - __bfloat162float(h[2]));
    h[3] = __float2bfloat16(v.w); l[3] = __float2bfloat16(v.w - __bfloat162float(h[3]));
    ((uint2*)hi)[j] = *(uint2*)h;
    ((uint2*)lo)[j] = *(uint2*)l;
}

// ---------------------------------------------------------------------------
// Combined projection: both q and k projections in ONE launch.
// blockIdx.x < 16 -> q proj tile; else k proj tile.
// C = relu(A @ W^T + bias), split-bf16 HMMA, virtual K = 3*1024.
// ---------------------------------------------------------------------------
#define PROJ_SMEM (1024 + 2 * 32768)

__global__ __launch_bounds__(256, 2) void proj_kernel(
    const float* __restrict__ q_b, const float* __restrict__ k_b) {
    extern __shared__ char smraw[];
    u32 braw = smem_u32(smraw);
    u32 base = (braw + 1023) & ~1023u;

    const int tid = threadIdx.x, lane = tid & 31, wid = tid >> 5;
    const bool isQ = blockIdx.x < 16;
    const int m0 = (isQ ? blockIdx.x : (blockIdx.x - 16)) * 128;
    const int n0 = blockIdx.y * 128;

    const __nv_bfloat16* Ahi = isQ ? g_seq_hi : g_key_hi;
    const __nv_bfloat16* Alo = isQ ? g_seq_lo : g_key_lo;
    const __nv_bfloat16* Whi = isQ ? g_qw_hi : g_kw_hi;
    const __nv_bfloat16* Wlo = isQ ? g_qw_lo : g_kw_lo;
    const float* bias = isQ ? q_b : k_b;
    __nv_bfloat16* Chi = isQ ? g_q_hi : g_k_hi;
    __nv_bfloat16* Clo = isQ ? g_q_lo : g_k_lo;

    const int wm0 = (wid >> 1) * 32, wn0 = (wid & 1) * 64;

    const __nv_bfloat16* segA[3] = {Ahi, Ahi, Alo};
    const __nv_bfloat16* segB[3] = {Whi, Wlo, Whi};

    const int r0l = tid >> 3, grp = tid & 7;

    auto load_chunk = [&](int c, int st) {
        int seg = c >> 4;
        int k0 = (c & 15) * 64;
        const __nv_bfloat16* As = segA[seg];
        const __nv_bfloat16* Bs = segB[seg];
        u32 Ab = base + (u32)st * 32768u;
        u32 Bb = Ab + 16384u;
#pragma unroll
        for (int g = 0; g < 4; g++) {
            int row = r0l + g * 32;
            u32 d = swz((u32)(row * 128 + grp * 16));
            CP_ASYNC16(Ab + d, As + (size_t)(m0 + row) * DIM + k0 + grp * 8);
            CP_ASYNC16(Bb + d, Bs + (size_t)(n0 + row) * DIM + k0 + grp * 8);
        }
        CP_COMMIT();
    };

    load_chunk(0, 0);
    load_chunk(1, 1);

    float acc[2][8][4];
#pragma unroll
    for (int i = 0; i < 2; i++)
#pragma unroll
        for (int j = 0; j < 8; j++)
#pragma unroll
            for (int q = 0; q < 4; q++) acc[i][j][q] = 0.f;

    const int lrA = wm0 + (lane & 15);
    const int lrB = wn0 + (lane & 15);
    const u32 khi = (u32)((lane >> 4) << 4);

    for (int c = 0; c < 48; c++) {
        const int st = c & 1;
        CP_WAIT(1);
        __syncthreads();
        u32 Ab = base + (u32)st * 32768u;
        u32 Bb = Ab + 16384u;
#pragma unroll
        for (int kk = 0; kk < 4; kk++) {
            u32 kb = (u32)(kk * 32) + khi;
            u32 a0[4], a1[4];
            ldsm4(a0[0], a0[1], a0[2], a0[3], Ab + swz((u32)(lrA * 128) + kb));
            ldsm4(a1[0], a1[1], a1[2], a1[3], Ab + swz((u32)((lrA + 16) * 128) + kb));
            u32 b[8][2];
#pragma unroll
            for (int nn = 0; nn < 4; nn++) {
                u32 t0, t1, t2, t3;
                ldsm4(t0, t1, t2, t3, Bb + swz((u32)((lrB + nn * 16) * 128) + kb));
                b[2 * nn][0] = t0; b[2 * nn + 1][0] = t1;
                b[2 * nn][1] = t2; b[2 * nn + 1][1] = t3;
            }
#pragma unroll
            for (int ni = 0; ni < 8; ni++) {
                mma16816(acc[0][ni], a0, b[ni]);
                mma16816(acc[1][ni], a1, b[ni]);
            }
        }
        __syncthreads();
        if (c + 2 < 48) load_chunk(c + 2, st);
    }

    const int g = lane >> 2, tg = lane & 3;
#pragma unroll
    for (int ni = 0; ni < 8; ni++) {
        int n = n0 + wn0 + ni * 8 + 2 * tg;
        float b0 = bias[n], b1 = bias[n + 1];
#pragma unroll
        for (int mi = 0; mi < 2; mi++) {
#pragma unroll
            for (int half = 0; half < 2; half++) {
                int m = m0 + wm0 + mi * 16 + half * 8 + g;
                float v0 = fmaxf(acc[mi][ni][half * 2 + 0] + b0, 0.f);
                float v1 = fmaxf(acc[mi][ni][half * 2 + 1] + b1, 0.f);
                __nv_bfloat16 h0 = __float2bfloat16(v0);
                __nv_bfloat16 h1 = __float2bfloat16(v1);
                __nv_bfloat16 l0 = __float2bfloat16(v0 - __bfloat162float(h0));
                __nv_bfloat16 l1 = __float2bfloat16(v1 - __bfloat162float(h1));
                __nv_bfloat162 hp; hp.x = h0; hp.y = h1;
                __nv_bfloat162 lp; lp.x = l0; lp.y = l1;
                *(__nv_bfloat162*)(Chi + (size_t)m * DIM + n) = hp;
                *(__nv_bfloat162*)(Clo + (size_t)m * DIM + n) = lp;
            }
        }
    }
}

// ---------------------------------------------------------------------------
// Energy: p[bh,t,s] = sigmoid(5*(q.k*0.125 + eb)), split-bf16 HMMA.
// ---------------------------------------------------------------------------
#define EN_SMEM (1024 + 3 * 32768)

__device__ __forceinline__ float sigmoid5(float e) {
    return 1.f / (1.f + __expf(-5.f * e));
}

__global__ __launch_bounds__(256, 2) void energy_kernel(
    const float* __restrict__ ebias, float* __restrict__ p) {
    extern __shared__ char smraw[];
    u32 braw = smem_u32(smraw);
    u32 base = (braw + 1023) & ~1023u;

    const int tid = threadIdx.x, lane = tid & 31, wid = tid >> 5;
    const int s0 = blockIdx.x * 128, t0 = blockIdx.y * 128;
    const int bh = blockIdx.z;
    const int b = bh >> 4, h = bh & 15;
    const int wm0 = (wid >> 1) * 32, wn0 = (wid & 1) * 64;

    const __nv_bfloat16* segQ[3] = {g_q_hi, g_q_hi, g_q_lo};
    const __nv_bfloat16* segK[3] = {g_k_hi, g_k_lo, g_k_hi};

    const int r0l = tid >> 3, grp = tid & 7;

#pragma unroll
    for (int c = 0; c < 3; c++) {
        const __nv_bfloat16* Qs = segQ[c];
        const __nv_bfloat16* Ks = segK[c];
        u32 Qb = base + (u32)c * 32768u;
        u32 Kb = Qb + 16384u;
#pragma unroll
        for (int g = 0; g < 4; g++) {
            int row = r0l + g * 32;
            u32 d = swz((u32)(row * 128 + grp * 16));
            CP_ASYNC16(Qb + d, Qs + (size_t)(b * TGT + t0 + row) * DIM + h * DH + grp * 8);
            CP_ASYNC16(Kb + d, Ks + (size_t)(b * SRC + s0 + row) * DIM + h * DH + grp * 8);
        }
        CP_COMMIT();
    }
    CP_WAIT(0);
    __syncthreads();

    float acc[2][8][4];
#pragma unroll
    for (int i = 0; i < 2; i++)
#pragma unroll
        for (int j = 0; j < 8; j++)
#pragma unroll
            for (int q = 0; q < 4; q++) acc[i][j][q] = 0.f;

    const int lrA = wm0 + (lane & 15);
    const int lrB = wn0 + (lane & 15);
    const u32 khi_off = (u32)((lane >> 4) << 4);

#pragma unroll
    for (int c = 0; c < 3; c++) {
        u32 Qb = base + (u32)c * 32768u;
        u32 Kb = Qb + 16384u;
#pragma unroll
        for (int kk = 0; kk < 4; kk++) {
            u32 kb = (u32)(kk * 32) + khi_off;
            u32 a0[4], a1[4];
            ldsm4(a0[0], a0[1], a0[2], a0[3], Qb + swz((u32)(lrA * 128) + kb));
            ldsm4(a1[0], a1[1], a1[2], a1[3], Qb + swz((u32)((lrA + 16) * 128) + kb));
            u32 bb[8][2];
#pragma unroll
            for (int nn = 0; nn < 4; nn++) {
                u32 t0r, t1r, t2r, t3r;
                ldsm4(t0r, t1r, t2r, t3r, Kb + swz((u32)((lrB + nn * 16) * 128) + kb));
                bb[2 * nn][0] = t0r; bb[2 * nn + 1][0] = t1r;
                bb[2 * nn][1] = t2r; bb[2 * nn + 1][1] = t3r;
            }
#pragma unroll
            for (int ni = 0; ni < 8; ni++) {
                mma16816(acc[0][ni], a0, bb[ni]);
                mma16816(acc[1][ni], a1, bb[ni]);
            }
        }
    }

    const float eb = ebias[0];
    const int g = lane >> 2, tg = lane & 3;
#pragma unroll
    for (int ni = 0; ni < 8; ni++) {
        int s = s0 + wn0 + ni * 8 + 2 * tg;
#pragma unroll
        for (int mi = 0; mi < 2; mi++) {
#pragma unroll
            for (int half = 0; half < 2; half++) {
                int t = t0 + wm0 + mi * 16 + half * 8 + g;
                float2 o;
                o.x = sigmoid5(acc[mi][ni][half * 2 + 0] * 0.125f + eb);
                o.y = sigmoid5(acc[mi][ni][half * 2 + 1] * 0.125f + eb);
                *(float2*)(p + ((size_t)bh * TGT + t) * SRC + s) = o;
            }
        }
    }
}

// ---------------------------------------------------------------------------
// Monotonic alignment: one WARP per bh, 2 t-steps per warp scan.
// Shortened critical path: two independent 8-elem serial chains (ILP=2),
// one compose, 5-round warp scan on lane totals, then seed-recompute of the
// two 8-elem chains (no per-element P arrays).
// ---------------------------------------------------------------------------
__global__ __launch_bounds__(32) void align_kernel(
    const float* __restrict__ p, float* __restrict__ alpha) {
    const int bh = blockIdx.x;
    const int lane = threadIdx.x;
    const float* prow = p + (size_t)bh * TGT * SRC + lane * 16;
    float* arow = alpha + (size_t)bh * TGT * SRC + lane * 16;

    float b[16];
#pragma unroll
    for (int i = 0; i < 16; i++) b[i] = 0.f;
    if (lane == 0) b[0] = 1.f;

    float4 f[8];
#pragma unroll
    for (int j = 0; j < 4; j++) {
        f[j]     = *(const float4*)(prow + 0 * SRC + 4 * j);
        f[4 + j] = *(const float4*)(prow + 1 * SRC + 4 * j);
    }

    for (int tp = 0; tp < TGT / 2; tp++) {
        float pt[16], pt1[16];
#pragma unroll
        for (int j = 0; j < 4; j++) {
            pt[4 * j + 0] = f[j].x;  pt[4 * j + 1] = f[j].y;
            pt[4 * j + 2] = f[j].z;  pt[4 * j + 3] = f[j].w;
            pt1[4 * j + 0] = f[4 + j].x; pt1[4 * j + 1] = f[4 + j].y;
            pt1[4 * j + 2] = f[4 + j].z; pt1[4 * j + 3] = f[4 + j].w;
        }
        if (tp + 1 < TGT / 2) {
            const float* np = prow + (size_t)(2 * tp + 2) * SRC;
#pragma unroll
            for (int j = 0; j < 4; j++) {
                f[j]     = *(const float4*)(np + 4 * j);
                f[4 + j] = *(const float4*)(np + SRC + 4 * j);
            }
        }

        float ptm  = __shfl_up_sync(0xffffffffu, pt[15], 1);
        float pt1m = __shfl_up_sync(0xffffffffu, pt1[15], 1);
        float at_first  = lane ? (1.f - ptm)  : 0.f;
        float at1_first = lane ? (1.f - pt1m) : 0.f;

        // two independent 8-element local chains (seed = 0)
        float C00[2], C10[2], C11[2], LX[2], LY[2];
#pragma unroll
        for (int h = 0; h < 2; h++) {
            float c00 = 1.f, c10 = 0.f, c11 = 1.f, x = 0.f, y = 0.f;
#pragma unroll
            for (int i = 0; i < 8; i++) {
                int e = h * 8 + i;
                float at  = (e == 0) ? at_first  : (1.f - pt[e - 1]);
                float at1 = (e == 0) ? at1_first : (1.f - pt1[e - 1]);
                x = fmaf(at, x, b[e]);
                y = fmaf(at1, y, pt[e] * x);
                c00 = at * c00;
                c10 = fmaf(pt[e], c00, at1 * c10);
                c11 = at1 * c11;
            }
            C00[h] = c00; C10[h] = c10; C11[h] = c11; LX[h] = x; LY[h] = y;
        }

        // lane total = M1 ∘ M0
        float s00 = C00[1] * C00[0];
        float s10 = fmaf(C10[1], C00[0], C11[1] * C10[0]);
        float s11 = C11[1] * C11[0];
        float X   = fmaf(C00[1], LX[0], LX[1]);
        float Y   = fmaf(C10[1], LX[0], fmaf(C11[1], LY[0], LY[1]));

        // warp inclusive scan of affine maps (P, V), branchless
#pragma unroll
        for (int d = 1; d < 32; d <<= 1) {
            float g00 = __shfl_up_sync(0xffffffffu, s00, d);
            float g10 = __shfl_up_sync(0xffffffffu, s10, d);
            float g11 = __shfl_up_sync(0xffffffffu, s11, d);
            float gX  = __shfl_up_sync(0xffffffffu, X, d);
            float gY  = __shfl_up_sync(0xffffffffu, Y, d);
            bool use = (lane >= d);
            float nX  = fmaf(s00, gX, X);
            float nY  = fmaf(s10, gX, fmaf(s11, gY, Y));
            float n00 = s00 * g00;
            float n10 = fmaf(s10, g00, s11 * g10);
            float n11 = s11 * g11;
            X = use ? nX : X;   Y = use ? nY : Y;
            s00 = use ? n00 : s00; s10 = use ? n10 : s10; s11 = use ? n11 : s11;
        }
        float Xin = __shfl_up_sync(0xffffffffu, X, 1);
        float Yin = __shfl_up_sync(0xffffffffu, Y, 1);
        Xin = lane ? Xin : 0.f;
        Yin = lane ? Yin : 0.f;

        // half seeds: half0 = (Xin,Yin); half1 = M0 applied to (Xin,Yin)
        float SX[2], SY[2];
        SX[0] = Xin;
        SY[0] = Yin;
        SX[1] = fmaf(C00[0], Xin, LX[0]);
        SY[1] = fmaf(C10[0], Xin, fmaf(C11[0], Yin, LY[0]));

        // seed-recompute the two chains (independent, ILP=2) + outputs
        float ot[16];
#pragma unroll
        for (int h = 0; h < 2; h++) {
            float x = SX[h], y = SY[h];
#pragma unroll
            for (int i = 0; i < 8; i++) {
                int e = h * 8 + i;
                float at  = (e == 0) ? at_first  : (1.f - pt[e - 1]);
                float at1 = (e == 0) ? at1_first : (1.f - pt1[e - 1]);
                x = fmaf(at, x, b[e]);
                float o = pt[e] * x;
                y = fmaf(at1, y, o);
                ot[e] = o;
                b[e] = pt1[e] * y;
            }
        }
        float* a0 = arow + (size_t)(2 * tp) * SRC;
        float* a1 = a0 + SRC;
#pragma unroll
        for (int j = 0; j < 4; j++) {
            *(float4*)(a0 + 4 * j) = make_float4(ot[4 * j], ot[4 * j + 1], ot[4 * j + 2], ot[4 * j + 3]);
            *(float4*)(a1 + 4 * j) = make_float4(b[4 * j], b[4 * j + 1], b[4 * j + 2], b[4 * j + 3]);
        }
    }
}

// ---------------------------------------------------------------------------
extern "C" void kernel_launch(void* const* d_in, const int* in_sizes, int n_in,
                              void* d_out, int out_size) {
    const float* seqs = (const float*)d_in[0];
    const float* keys = (const float*)d_in[1];
    const float* q_w  = (const float*)d_in[2];
    const float* q_b  = (const float*)d_in[3];
    const float* k_w  = (const float*)d_in[4];
    const float* k_b  = (const float*)d_in[5];
    const float* eb   = (const float*)d_in[6];

    float* out   = (float*)d_out;
    float* p     = out;
    float* alpha = out + (size_t)NB * NH * TGT * SRC;

    cudaFuncSetAttribute(proj_kernel, cudaFuncAttributeMaxDynamicSharedMemorySize, PROJ_SMEM);
    cudaFuncSetAttribute(energy_kernel, cudaFuncAttributeMaxDynamicSharedMemorySize, EN_SMEM);

    // fused fp32 -> bf16 hi/lo splits (one launch)
    split_all_kernel<<<(N4_TOT + 255) / 256, 256>>>(seqs, keys, q_w, k_w);

    // both projections in one launch (x: 16 q-tiles + 32 k-tiles)
    proj_kernel<<<dim3(48, DIM / 128), 256, PROJ_SMEM>>>(q_b, k_b);

    // p_choose (HMMA)
    energy_kernel<<<dim3(SRC / 128, TGT / 128, NB * NH), 256, EN_SMEM>>>(eb, p);

    // alpha
    align_kernel<<<NB * NH, 32>>>(p, alpha);
}